// round 6
// baseline (speedup 1.0000x reference)
#include <cuda_runtime.h>
#include <math.h>

// Sign convention for C222: reference fixes sign via argmax(|c|) over a 7-way
// tie broken by LAPACK noise. R4 measured rel_err=1.51 with -1.0 => the
// reference's argmax landed on the (0,0,0) entry; correct convention is +1.0
// (C[2][2][2] > 0).
#define C62_SIGN (+1.0)

// ---- packed weight layout (floats) ----
#define OFF_W000S 0
#define OFF_W110S 4352
#define OFF_W011  5792
#define OFF_W101  10400
#define OFF_W111S 15008
#define OFF_V110T 16448
#define OFF_VSUM  17472
#define OFF_C     18496
#define WTOT      18624
#define OFF_PAIRS 18624      /* 48 ints */
#define SCRBASE   18672

// ---- per-warp scratch (floats) ----
#define U1_   328
#define U2_   556
#define H2S_  916
#define AS_   1172
#define H0S_  1428
#define SCR_  1464

#define NWARPS 16
#define NTHREADS 512
#define SMEM_FLOATS (SCRBASE + NWARPS * SCR_)
#define SMEM_BYTES  (SMEM_FLOATS * 4)

__device__ float gPack[WTOT];

// =======================================================================
// prep: compute C222 (Casimir projection, fp64) + fold/symmetrize weights
// =======================================================================
__global__ void prep_kernel(const float* __restrict__ w000, const float* __restrict__ w110,
                            const float* __restrict__ w011, const float* __restrict__ w101,
                            const float* __restrict__ w111, const float* __restrict__ v010,
                            const float* __restrict__ v100, const float* __restrict__ v110)
{
    __shared__ double sG[3][25];
    __shared__ double sv[125], su[125], sw2[125];
    __shared__ int sPU16[136], sPV16[136], sPU9[45], sPV9[45];
    __shared__ double sscale;

    int tid = threadIdx.x;
    if (tid == 0) {
        int idx = 0;
        for (int u = 0; u < 16; u++) for (int v = u; v < 16; v++) { sPU16[idx]=u; sPV16[idx]=v; idx++; }
        idx = 0;
        for (int u = 0; u < 9; u++) for (int v = u; v < 9; v++) { sPU9[idx]=u; sPV9[idx]=v; idx++; }

        double Jp[5][5];
        for (int i=0;i<5;i++) for (int j=0;j<5;j++) Jp[i][j]=0.0;
        for (int i=0;i<4;i++){ double m = -2.0 + i; Jp[i+1][i] = sqrt(6.0 - m*(m+1.0)); }
        double Jre[3][5][5], Jim[3][5][5];
        for (int a=0;a<3;a++) for (int i=0;i<5;i++) for (int j=0;j<5;j++){ Jre[a][i][j]=0.0; Jim[a][i][j]=0.0; }
        for (int i=0;i<5;i++) for (int j=0;j<5;j++){
            Jre[0][i][j] =  0.5*(Jp[i][j] + Jp[j][i]);
            Jim[1][i][j] = -0.5*(Jp[i][j] - Jp[j][i]);
        }
        for (int i=0;i<5;i++) Jre[2][i][i] = (double)(i - 2);

        double Qre[5][5], Qim[5][5];
        for (int i=0;i<5;i++) for (int j=0;j<5;j++){ Qre[i][j]=0.0; Qim[i][j]=0.0; }
        double is2 = 1.0 / sqrt(2.0);
        for (int m=-2;m<=2;m++){
            int i = m + 2;
            double pm = ((m & 1) != 0) ? -1.0 : 1.0;
            if (m < 0)      { Qim[i][i] = is2; Qim[i][2 - m] = -pm * is2; }
            else if (m==0)  { Qre[i][i] = 1.0; }
            else            { Qre[i][2 - m] = is2; Qre[i][i] = pm * is2; }
        }
        for (int a=0;a<3;a++){
            double T1re[5][5], T1im[5][5];
            for (int i=0;i<5;i++) for (int j=0;j<5;j++){
                double re=0.0, im=0.0;
                for (int p=0;p<5;p++){
                    re += Qre[i][p]*Jre[a][p][j] - Qim[i][p]*Jim[a][p][j];
                    im += Qre[i][p]*Jim[a][p][j] + Qim[i][p]*Jre[a][p][j];
                }
                T1re[i][j]=re; T1im[i][j]=im;
            }
            for (int i=0;i<5;i++) for (int j=0;j<5;j++){
                double im=0.0;
                for (int p=0;p<5;p++)
                    im += T1im[i][p]*Qre[j][p] - T1re[i][p]*Qim[j][p];
                sG[a][i*5+j] = im;   // G = Im(Q J Q^H)
            }
        }
    }
    __syncthreads();

    if (tid < 125) { double x = sin((double)(tid + 1) * 12.9898) * 43758.5453; sv[tid] = x - floor(x) - 0.5; }
    __syncthreads();

    const double lambdas[6] = {2.0, 6.0, 12.0, 20.0, 30.0, 42.0};
    int i1 = tid / 25, i2 = (tid / 5) % 5, i3 = tid % 5;
    for (int st = 0; st < 6; st++) {
        double accv = (tid < 125) ? (-lambdas[st] * sv[tid]) : 0.0;
        for (int a = 0; a < 3; a++) {
            if (tid < 125) {
                double r = 0.0;
                for (int p = 0; p < 5; p++) {
                    r += sG[a][i1*5+p] * sv[p*25 + i2*5 + i3];
                    r += sG[a][i2*5+p] * sv[i1*25 + p*5 + i3];
                    r += sG[a][i3*5+p] * sv[i1*25 + i2*5 + p];
                }
                su[tid] = r;
            }
            __syncthreads();
            if (tid < 125) {
                double r = 0.0;
                for (int p = 0; p < 5; p++) {
                    r += sG[a][i1*5+p] * su[p*25 + i2*5 + i3];
                    r += sG[a][i2*5+p] * su[i1*25 + p*5 + i3];
                    r += sG[a][i3*5+p] * su[i1*25 + i2*5 + p];
                }
                sw2[tid] = r;
            }
            __syncthreads();
            if (tid < 125) accv -= sw2[tid];   // A = -sum G_tot^2
            __syncthreads();
        }
        if (tid < 125) sv[tid] = accv;         // v <- (A - lambda I) v
        __syncthreads();
    }
    if (tid == 0) {
        double n2 = 0.0;
        for (int i = 0; i < 125; i++) n2 += sv[i]*sv[i];
        // deterministic sign rule: sign(C[2][2][2]) == C62_SIGN
        double sgn = (sv[62] * C62_SIGN > 0.0) ? 1.0 : -1.0;
        sscale = sgn / sqrt(n2);
    }
    __syncthreads();
    if (tid < 125) gPack[OFF_C + tid] = (float)(sv[tid] * sscale);
    if (tid >= 125 && tid < 128) gPack[OFF_C + tid] = 0.f;

    const double c0 = 1.0 / sqrt(337.0);
    const double c2 = sqrt(5.0 / 369.0);
    const double dd = sqrt(5.0 / 3072.0);
    const double i5 = 1.0 / sqrt(5.0);

    for (int idx = tid; idx < 136*32; idx += blockDim.x) {
        int p = idx >> 5, w = idx & 31, u = sPU16[p], v = sPV16[p];
        float val = (u == v) ? w000[(u*16+u)*32 + w]
                             : (w000[(u*16+v)*32 + w] + w000[(v*16+u)*32 + w]);
        gPack[OFF_W000S + idx] = (float)c0 * val;
    }
    for (int idx = tid; idx < 45*32; idx += blockDim.x) {
        int p = idx >> 5, w = idx & 31, u = sPU9[p], v = sPV9[p];
        float v1 = (u == v) ? w110[(u*9+u)*32 + w]
                            : (w110[(u*9+v)*32 + w] + w110[(v*9+u)*32 + w]);
        gPack[OFF_W110S + idx] = (float)(c0 * i5) * v1;
        float v2 = (u == v) ? w111[(u*9+u)*32 + w]
                            : (w111[(u*9+v)*32 + w] + w111[(v*9+u)*32 + w]);
        gPack[OFF_W111S + idx] = (float)c2 * v2;
    }
    for (int idx = tid; idx < 4608; idx += blockDim.x) {
        gPack[OFF_W011 + idx] = (float)(c2 * i5) * w011[idx];
        gPack[OFF_W101 + idx] = (float)(c2 * i5) * w101[idx];
    }
    for (int idx = tid; idx < 1024; idx += blockDim.x) {
        int u = idx >> 5, v = idx & 31;
        gPack[OFF_V110T + v*32 + u] = (float)dd * v110[idx];
        gPack[OFF_VSUM  + idx]      = (float)(dd * i5) * (v010[idx] + v100[v*32 + u]);
    }
}

// =======================================================================
// main: warp per element, H=32 -> lanes
// =======================================================================
__global__ void __launch_bounds__(NTHREADS, 1)
eq_head_kernel(const float* __restrict__ scalars, const float* __restrict__ kt,
               float* __restrict__ outp, int NB, int NK)
{
    extern __shared__ float sm[];
    for (int i = threadIdx.x; i < WTOT; i += NTHREADS) sm[i] = gPack[i];
    int* sPairs = (int*)(sm + OFF_PAIRS);
    if (threadIdx.x < 48) {
        int p = threadIdx.x, val = 0;
        if (p < 45) {
            const int RT[9] = {0, 8, 16, 32, 192, 208, 280, 304, 320};
            int u = 0, acc = 0;
            while (acc + (9 - u) <= p) { acc += 9 - u; u++; }
            int v = u + (p - acc);
            val = (u * 25) | (RT[u] << 8) | (RT[v] << 20);
        }
        sPairs[p] = val;
    }
    __syncthreads();

    const float* sW000S = sm + OFF_W000S;
    const float* sW110S = sm + OFF_W110S;
    const float* sW011  = sm + OFF_W011;
    const float* sW101  = sm + OFF_W101;
    const float* sW111S = sm + OFF_W111S;
    const float* sV110T = sm + OFF_V110T;
    const float* sVSUM  = sm + OFF_VSUM;
    const float* sCt    = sm + OFF_C;

    const int lane = threadIdx.x & 31;
    const int warp = threadIdx.x >> 5;
    float* scr = sm + SCRBASE + warp * SCR_;

    const int gw = blockIdx.x * NWARPS + warp;
    const int TW = gridDim.x * NWARPS;
    const int RN = NK * 5;
    const int ROW8[9] = {0, 8, 16, 32, 192, 208, 280, 304, 320};
    const int pl = lane / 5, kk = lane - pl * 5;

    for (int e = gw; e < NB; e += TW) {
        // -- load kernel row into R8 layout (n*8+i), scalars to regs --
        const float* ke = kt + (size_t)e * RN;
        for (int m = lane; m < RN; m += 32) {
            float v = __ldg(ke + m);
            int n = m / 5, i = m - n * 5;
            scr[n * 8 + i] = v;
        }
        const float4* sp4 = (const float4*)(scalars + (size_t)e * 16);
        float4 sA = __ldg(sp4), sB = __ldg(sp4 + 1), sC4 = __ldg(sp4 + 2), sD = __ldg(sp4 + 3);
        float s_[16] = {sA.x, sA.y, sA.z, sA.w, sB.x, sB.y, sB.z, sB.w,
                        sC4.x, sC4.y, sC4.z, sC4.w, sD.x, sD.y, sD.z, sD.w};
        __syncwarp();
        // -- kernel sum row at offset 320 --
        if (lane < 5) {
            float a = 0.f;
            for (int n = 0; n < NK; n++) a += scr[n * 8 + lane];
            scr[320 + lane] = a;
        }
        __syncwarp();

        // -- Gram g[p] (into AS region) --
        #pragma unroll
        for (int r = 0; r < 2; r++) {
            int p = lane + 32 * r;
            if (p < 45) {
                int t3 = sPairs[p];
                int ru = (t3 >> 8) & 0x1FF, rv = t3 >> 20;
                float acc = 0.f;
                #pragma unroll
                for (int i = 0; i < 5; i++) acc = fmaf(scr[ru + i], scr[rv + i], acc);
                scr[AS_ + p] = acc;
            }
        }

        // -- h0: w000S part --
        float h0 = 0.f;
        {
            int p = 0;
            #pragma unroll
            for (int u = 0; u < 16; u++) {
                #pragma unroll
                for (int v = u; v < 16; v++) { h0 = fmaf(sW000S[p*32 + lane], s_[u]*s_[v], h0); p++; }
            }
        }
        __syncwarp();
        #pragma unroll
        for (int p = 0; p < 45; p++) h0 = fmaf(sW110S[p*32 + lane], scr[AS_ + p], h0);

        // -- h2 terms 1+2: (w011.s + w101.s) * t_r[k] --
        float h2r0=0.f,h2r1=0.f,h2r2=0.f,h2r3=0.f,h2r4=0.f;
        #pragma unroll
        for (int t9 = 0; t9 < 9; t9++) {
            const int ro = ROW8[t9];
            float4 t4 = *(const float4*)(scr + ro);
            float t4w = scr[ro + 4];
            float a = 0.f;
            #pragma unroll
            for (int u = 0; u < 16; u++) a = fmaf(sW011[(u*9 + t9)*32 + lane], s_[u], a);
            #pragma unroll
            for (int v = 0; v < 16; v++) a = fmaf(sW101[(t9*16 + v)*32 + lane], s_[v], a);
            h2r0 = fmaf(a, t4.x, h2r0); h2r1 = fmaf(a, t4.y, h2r1);
            h2r2 = fmaf(a, t4.z, h2r2); h2r3 = fmaf(a, t4.w, h2r3);
            h2r4 = fmaf(a, t4w,  h2r4);
        }

        // -- u1[u][jk] = sum_i t_u[i] C[i*25+jk] (lanes 0..24) --
        #pragma unroll
        for (int u = 0; u < 9; u++) {
            const int ro = ROW8[u];
            if (lane < 25) {
                float4 t4 = *(const float4*)(scr + ro);
                float t4w = scr[ro + 4];
                float acc = t4.x * sCt[lane]      + t4.y * sCt[25 + lane]
                          + t4.z * sCt[50 + lane] + t4.w * sCt[75 + lane]
                          + t4w  * sCt[100 + lane];
                scr[U1_ + u*25 + lane] = acc;
            }
        }
        __syncwarp();

        // -- u2[p][k] = sum_j u1[u][j*5+k] * t_v[j] --
        #pragma unroll
        for (int r = 0; r < 8; r++) {
            int p = r * 6 + pl;
            if (lane < 30 && p < 45) {
                int t3 = sPairs[p];
                int u25 = t3 & 0xFF, rv = t3 >> 20;
                float acc = 0.f;
                #pragma unroll
                for (int j = 0; j < 5; j++)
                    acc = fmaf(scr[U1_ + u25 + j*5 + kk], scr[rv + j], acc);
                scr[U2_ + p*8 + kk] = acc;
            }
        }
        __syncwarp();

        // -- h2 term3: sum_p w111S[p][w] * u2[p][k] --
        #pragma unroll
        for (int p = 0; p < 45; p++) {
            float w = sW111S[p*32 + lane];
            float4 u4 = *(const float4*)(scr + U2_ + p*8);
            float u4w = scr[U2_ + p*8 + 4];
            h2r0 = fmaf(w, u4.x, h2r0); h2r1 = fmaf(w, u4.y, h2r1);
            h2r2 = fmaf(w, u4.z, h2r2); h2r3 = fmaf(w, u4.w, h2r3);
            h2r4 = fmaf(w, u4w,  h2r4);
        }

        // -- publish h2, h0 --
        *(float4*)(scr + H2S_ + lane*8) = make_float4(h2r0, h2r1, h2r2, h2r3);
        scr[H2S_ + lane*8 + 4] = h2r4;
        scr[H0S_ + lane] = h0;
        __syncwarp();

        // -- a[w][j] = sum_v v110T[v][w] h2[v][j] (d folded) --
        float a0=0.f,a1=0.f,a2=0.f,a3=0.f,a4=0.f;
        #pragma unroll
        for (int v = 0; v < 32; v++) {
            float w = sV110T[v*32 + lane];
            float4 h4 = *(const float4*)(scr + H2S_ + v*8);
            float h4w = scr[H2S_ + v*8 + 4];
            a0 = fmaf(w, h4.x, a0); a1 = fmaf(w, h4.y, a1);
            a2 = fmaf(w, h4.z, a2); a3 = fmaf(w, h4.w, a3);
            a4 = fmaf(w, h4w,  a4);
        }
        *(float4*)(scr + AS_ + lane*8) = make_float4(a0, a1, a2, a3);
        scr[AS_ + lane*8 + 4] = a4;

        // -- r[w] = sum_m VSUM[m][w] * h0[m] --
        float rr = 0.f;
        #pragma unroll
        for (int m = 0; m < 32; m++) rr = fmaf(sVSUM[m*32 + lane], scr[H0S_ + m], rr);
        __syncwarp();

        // -- final: vk[k] = r*h2[w][k] + (lane<25: b2[ij]*C[ij][k]); warp reduce --
        float vk0 = rr*h2r0, vk1 = rr*h2r1, vk2 = rr*h2r2, vk3 = rr*h2r3, vk4 = rr*h2r4;
        if (lane < 25) {
            float b2 = 0.f;
            #pragma unroll
            for (int u = 0; u < 32; u++)
                b2 = fmaf(scr[H2S_ + u*8 + pl], scr[AS_ + u*8 + kk], b2);
            vk0 = fmaf(b2, sCt[lane*5 + 0], vk0);
            vk1 = fmaf(b2, sCt[lane*5 + 1], vk1);
            vk2 = fmaf(b2, sCt[lane*5 + 2], vk2);
            vk3 = fmaf(b2, sCt[lane*5 + 3], vk3);
            vk4 = fmaf(b2, sCt[lane*5 + 4], vk4);
        }
        #pragma unroll
        for (int off = 16; off > 0; off >>= 1) {
            vk0 += __shfl_xor_sync(0xffffffffu, vk0, off);
            vk1 += __shfl_xor_sync(0xffffffffu, vk1, off);
            vk2 += __shfl_xor_sync(0xffffffffu, vk2, off);
            vk3 += __shfl_xor_sync(0xffffffffu, vk3, off);
            vk4 += __shfl_xor_sync(0xffffffffu, vk4, off);
        }
        if (lane == 0) {
            float* o = outp + (size_t)e * 5;
            o[0] = vk0; o[1] = vk1; o[2] = vk2; o[3] = vk3; o[4] = vk4;
        }
    }
}

extern "C" void kernel_launch(void* const* d_in, const int* in_sizes, int n_in,
                              void* d_out, int out_size) {
    const float* scalars = (const float*)d_in[0];
    const float* kt      = (const float*)d_in[1];
    const float* w000    = (const float*)d_in[2];
    const float* w110    = (const float*)d_in[3];
    const float* w011    = (const float*)d_in[4];
    const float* w101    = (const float*)d_in[5];
    const float* w111    = (const float*)d_in[6];
    const float* v010    = (const float*)d_in[7];
    const float* v100    = (const float*)d_in[8];
    const float* v110    = (const float*)d_in[9];
    float* out = (float*)d_out;

    int B = in_sizes[0] / 16;
    int NK = (B > 0) ? in_sizes[1] / (B * 5) : 40;

    prep_kernel<<<1, 512>>>(w000, w110, w011, w101, w111, v010, v100, v110);

    cudaFuncSetAttribute(eq_head_kernel, cudaFuncAttributeMaxDynamicSharedMemorySize, SMEM_BYTES);
    eq_head_kernel<<<296, NTHREADS, SMEM_BYTES>>>(scalars, kt, out, B, NK);
}

// round 12
// speedup vs baseline: 1.2940x; 1.2940x over previous
#include <cuda_runtime.h>
#include <math.h>

// C222 sign convention (verified R6): C[2][2][2] > 0.
#define C62_SIGN (+1.0)

// ---- packed weight layout (floats) ----
#define OFF_W000S 0        /* 136*32 */
#define OFF_W110S 4352     /* 45*32  */
#define OFF_W011C 5792     /* 144*32 (w011 + w101^T folded) */
#define OFF_W111S 10400    /* 45*32  */
#define OFF_V110T 11840    /* 32*32  */
#define OFF_VSUM  12864    /* 32*32  */
#define OFF_C     13888    /* 125 pad 128 */
#define WTOT      14016
#define OFF_PAIRS 14016    /* 48 ints */
#define SCRBASE   14064

// ---- per-warp-per-element scratch (floats), liveness-aliased ----
#define ROWb  0            /* 40*8 + 5 sum + pad = 328 */
#define U1b   328          /* 225 pad 228; aliased by Ab later */
#define Gb    556          /* 45 gram; aliased by U2b later */
#define U2b   556          /* 45*8 = 360, ends 916 */
#define Ab    328          /* 32*8 = 256 'a' matrix, written after U2 consumed */
#define H2b   916          /* 32*8 = 256 */
#define H0b   1172         /* 32 */
#define SCR_  1208

#define NWARPS   16
#define NTHREADS 512
#define SMEM_FLOATS (SCRBASE + NWARPS * 2 * SCR_)
#define SMEM_BYTES  (SMEM_FLOATS * 4)

__device__ float gPack[WTOT];

// =======================================================================
// prep_c: compute C222 via fp64 Casimir-polynomial projection (1 block)
// =======================================================================
__global__ void prep_c_kernel()
{
    __shared__ double sG[3][25];
    __shared__ double sv[125], su[125], sw2[125];
    __shared__ double sscale;

    int tid = threadIdx.x;
    if (tid == 0) {
        double Jp[5][5];
        for (int i=0;i<5;i++) for (int j=0;j<5;j++) Jp[i][j]=0.0;
        for (int i=0;i<4;i++){ double m = -2.0 + i; Jp[i+1][i] = sqrt(6.0 - m*(m+1.0)); }
        double Jre[3][5][5], Jim[3][5][5];
        for (int a=0;a<3;a++) for (int i=0;i<5;i++) for (int j=0;j<5;j++){ Jre[a][i][j]=0.0; Jim[a][i][j]=0.0; }
        for (int i=0;i<5;i++) for (int j=0;j<5;j++){
            Jre[0][i][j] =  0.5*(Jp[i][j] + Jp[j][i]);
            Jim[1][i][j] = -0.5*(Jp[i][j] - Jp[j][i]);
        }
        for (int i=0;i<5;i++) Jre[2][i][i] = (double)(i - 2);

        double Qre[5][5], Qim[5][5];
        for (int i=0;i<5;i++) for (int j=0;j<5;j++){ Qre[i][j]=0.0; Qim[i][j]=0.0; }
        double is2 = 1.0 / sqrt(2.0);
        for (int m=-2;m<=2;m++){
            int i = m + 2;
            double pm = ((m & 1) != 0) ? -1.0 : 1.0;
            if (m < 0)      { Qim[i][i] = is2; Qim[i][2 - m] = -pm * is2; }
            else if (m==0)  { Qre[i][i] = 1.0; }
            else            { Qre[i][2 - m] = is2; Qre[i][i] = pm * is2; }
        }
        for (int a=0;a<3;a++){
            double T1re[5][5], T1im[5][5];
            for (int i=0;i<5;i++) for (int j=0;j<5;j++){
                double re=0.0, im=0.0;
                for (int p=0;p<5;p++){
                    re += Qre[i][p]*Jre[a][p][j] - Qim[i][p]*Jim[a][p][j];
                    im += Qre[i][p]*Jim[a][p][j] + Qim[i][p]*Jre[a][p][j];
                }
                T1re[i][j]=re; T1im[i][j]=im;
            }
            for (int i=0;i<5;i++) for (int j=0;j<5;j++){
                double im=0.0;
                for (int p=0;p<5;p++)
                    im += T1im[i][p]*Qre[j][p] - T1re[i][p]*Qim[j][p];
                sG[a][i*5+j] = im;   // G = Im(Q J Q^H)
            }
        }
    }
    __syncthreads();

    if (tid < 125) { double x = sin((double)(tid + 1) * 12.9898) * 43758.5453; sv[tid] = x - floor(x) - 0.5; }
    __syncthreads();

    const double lambdas[6] = {2.0, 6.0, 12.0, 20.0, 30.0, 42.0};
    int i1 = tid / 25, i2 = (tid / 5) % 5, i3 = tid % 5;
    for (int st = 0; st < 6; st++) {
        double accv = (tid < 125) ? (-lambdas[st] * sv[tid]) : 0.0;
        for (int a = 0; a < 3; a++) {
            if (tid < 125) {
                double r = 0.0;
                for (int p = 0; p < 5; p++) {
                    r += sG[a][i1*5+p] * sv[p*25 + i2*5 + i3];
                    r += sG[a][i2*5+p] * sv[i1*25 + p*5 + i3];
                    r += sG[a][i3*5+p] * sv[i1*25 + i2*5 + p];
                }
                su[tid] = r;
            }
            __syncthreads();
            if (tid < 125) {
                double r = 0.0;
                for (int p = 0; p < 5; p++) {
                    r += sG[a][i1*5+p] * su[p*25 + i2*5 + i3];
                    r += sG[a][i2*5+p] * su[i1*25 + p*5 + i3];
                    r += sG[a][i3*5+p] * su[i1*25 + i2*5 + p];
                }
                sw2[tid] = r;
            }
            __syncthreads();
            if (tid < 125) accv -= sw2[tid];   // A = -sum G_tot^2
            __syncthreads();
        }
        if (tid < 125) sv[tid] = accv;         // v <- (A - lambda I) v
        __syncthreads();
    }
    if (tid == 0) {
        double n2 = 0.0;
        for (int i = 0; i < 125; i++) n2 += sv[i]*sv[i];
        double sgn = (sv[62] * C62_SIGN > 0.0) ? 1.0 : -1.0;
        sscale = sgn / sqrt(n2);
    }
    __syncthreads();
    if (tid < 125) gPack[OFF_C + tid] = (float)(sv[tid] * sscale);
    if (tid >= 125 && tid < 128) gPack[OFF_C + tid] = 0.f;
}

// =======================================================================
// prep_fold: fold/symmetrize weights (parallel, many blocks)
// =======================================================================
__device__ __forceinline__ void tri_decode(int p, int N, int& u, int& v) {
    int uu = 0, rem = p;
    while (rem >= N - uu) { rem -= N - uu; uu++; }
    u = uu; v = uu + rem;
}

__global__ void prep_fold_kernel(const float* __restrict__ w000, const float* __restrict__ w110,
                                 const float* __restrict__ w011, const float* __restrict__ w101,
                                 const float* __restrict__ w111, const float* __restrict__ v010,
                                 const float* __restrict__ v100, const float* __restrict__ v110)
{
    const float c0 = (float)(1.0 / sqrt(337.0));
    const float c2 = (float)sqrt(5.0 / 369.0);
    const float dd = (float)sqrt(5.0 / 3072.0);
    const float i5 = (float)(1.0 / sqrt(5.0));

    int stride = gridDim.x * blockDim.x;
    int t0 = blockIdx.x * blockDim.x + threadIdx.x;

    for (int idx = t0; idx < 136*32; idx += stride) {
        int p = idx >> 5, w = idx & 31, u, v;
        tri_decode(p, 16, u, v);
        float val = (u == v) ? w000[(u*16+u)*32 + w]
                             : (w000[(u*16+v)*32 + w] + w000[(v*16+u)*32 + w]);
        gPack[OFF_W000S + idx] = c0 * val;
    }
    for (int idx = t0; idx < 45*32; idx += stride) {
        int p = idx >> 5, w = idx & 31, u, v;
        tri_decode(p, 9, u, v);
        float v1 = (u == v) ? w110[(u*9+u)*32 + w]
                            : (w110[(u*9+v)*32 + w] + w110[(v*9+u)*32 + w]);
        gPack[OFF_W110S + idx] = (c0 * i5) * v1;
        float v2 = (u == v) ? w111[(u*9+u)*32 + w]
                            : (w111[(u*9+v)*32 + w] + w111[(v*9+u)*32 + w]);
        gPack[OFF_W111S + idx] = c2 * v2;
    }
    for (int idx = t0; idx < 144*32; idx += stride) {
        int r = idx >> 5, w = idx & 31;
        int u = r / 9, t9 = r - u * 9;
        gPack[OFF_W011C + idx] = (c2 * i5) * (w011[idx] + w101[(t9*16 + u)*32 + w]);
    }
    for (int idx = t0; idx < 1024; idx += stride) {
        int u = idx >> 5, v = idx & 31;
        gPack[OFF_V110T + v*32 + u] = dd * v110[idx];
        gPack[OFF_VSUM  + idx]      = (dd * i5) * (v010[idx] + v100[v*32 + u]);
    }
}

// =======================================================================
// main: warp per 2 elements, H=32 -> lanes, weights amortized
// =======================================================================
__global__ void __launch_bounds__(NTHREADS, 1)
eq_head_kernel(const float* __restrict__ scalars, const float* __restrict__ kt,
               float* __restrict__ outp, int NB, int NK)
{
    extern __shared__ float sm[];
    for (int i = threadIdx.x; i < WTOT; i += NTHREADS) sm[i] = gPack[i];
    int* sPairs = (int*)(sm + OFF_PAIRS);
    if (threadIdx.x < 48) {
        int p = threadIdx.x, val = 0;
        if (p < 45) {
            const int RT[9] = {0, 8, 16, 32, 192, 208, 280, 304, 320};
            int u = 0, acc = 0;
            while (acc + (9 - u) <= p) { acc += 9 - u; u++; }
            int v = u + (p - acc);
            val = (u * 25) | (RT[u] << 8) | (RT[v] << 20);
        }
        sPairs[p] = val;
    }
    __syncthreads();

    const float* sW000S = sm + OFF_W000S;
    const float* sW110S = sm + OFF_W110S;
    const float* sW011C = sm + OFF_W011C;
    const float* sW111S = sm + OFF_W111S;
    const float* sV110T = sm + OFF_V110T;
    const float* sVSUM  = sm + OFF_VSUM;
    const float* sCt    = sm + OFF_C;

    const int lane = threadIdx.x & 31;
    const int warp = threadIdx.x >> 5;
    float* scr0 = sm + SCRBASE + warp * (2 * SCR_);
    float* scr1 = scr0 + SCR_;

    const int gw = blockIdx.x * NWARPS + warp;
    const int TW = gridDim.x * NWARPS;
    const int RN = NK * 5;
    const int ROW8[9] = {0, 8, 16, 32, 192, 208, 280, 304, 320};
    const int pl = lane / 5, kk = lane - pl * 5;

    for (int e = gw * 2; e < NB; e += TW * 2) {
        const int e0 = e;
        const int e1 = (e + 1 < NB) ? (e + 1) : e;   // clamp (NB even in practice)
        const bool has1 = (e + 1 < NB);

        // ---- load kt rows (R8 layout) for both elements ----
        const float* ke0 = kt + (size_t)e0 * RN;
        const float* ke1 = kt + (size_t)e1 * RN;
        for (int m = lane; m < RN; m += 32) {
            int n = m / 5, i = m - n * 5;
            scr0[n * 8 + i] = __ldg(ke0 + m);
            scr1[n * 8 + i] = __ldg(ke1 + m);
        }
        // ---- scalars to regs ----
        float s0_[16], s1_[16];
        {
            const float4* p0 = (const float4*)(scalars + (size_t)e0 * 16);
            const float4* p1 = (const float4*)(scalars + (size_t)e1 * 16);
            #pragma unroll
            for (int q = 0; q < 4; q++) {
                float4 a = __ldg(p0 + q), b = __ldg(p1 + q);
                s0_[q*4+0]=a.x; s0_[q*4+1]=a.y; s0_[q*4+2]=a.z; s0_[q*4+3]=a.w;
                s1_[q*4+0]=b.x; s1_[q*4+1]=b.y; s1_[q*4+2]=b.z; s1_[q*4+3]=b.w;
            }
        }
        __syncwarp();

        // ---- kernel-sum rows (dual-lane: 0-4 -> e0, 8-12 -> e1) ----
        {
            int li = lane & 7;
            float* sc = (lane < 8) ? scr0 : scr1;
            if (li < 5 && lane < 16) {
                float a = 0.f;
                for (int n = 0; n < NK; n++) a += sc[n * 8 + li];
                sc[320 + li] = a;
            }
        }
        __syncwarp();

        // ---- Gram g[p] for both ----
        #pragma unroll
        for (int r = 0; r < 2; r++) {
            int p = lane + 32 * r;
            if (p < 45) {
                int t3 = sPairs[p];
                int ru = (t3 >> 8) & 0xFFF, rv = t3 >> 20;
                float g0 = 0.f, g1 = 0.f;
                #pragma unroll
                for (int i = 0; i < 5; i++) {
                    g0 = fmaf(scr0[ru + i], scr0[rv + i], g0);
                    g1 = fmaf(scr1[ru + i], scr1[rv + i], g1);
                }
                scr0[Gb + p] = g0;
                scr1[Gb + p] = g1;
            }
        }

        // ---- h0: w000S part (register-only inputs) ----
        float h0a = 0.f, h0b = 0.f;
        {
            int p = 0;
            #pragma unroll
            for (int u = 0; u < 16; u++) {
                #pragma unroll
                for (int v = u; v < 16; v++) {
                    float w = sW000S[p*32 + lane];
                    h0a = fmaf(w, s0_[u]*s0_[v], h0a);
                    h0b = fmaf(w, s1_[u]*s1_[v], h0b);
                    p++;
                }
            }
        }
        __syncwarp();
        #pragma unroll
        for (int p = 0; p < 45; p++) {
            float w = sW110S[p*32 + lane];
            h0a = fmaf(w, scr0[Gb + p], h0a);
            h0b = fmaf(w, scr1[Gb + p], h0b);
        }

        // ---- h2 terms 1+2: folded (w011+w101^T).s times t[k] ----
        float A0=0.f,A1=0.f,A2=0.f,A3=0.f,A4=0.f;
        float B0=0.f,B1=0.f,B2=0.f,B3=0.f,B4=0.f;
        #pragma unroll
        for (int t9 = 0; t9 < 9; t9++) {
            const int ro = ROW8[t9];
            float4 ta = *(const float4*)(scr0 + ro);
            float  taw = scr0[ro + 4];
            float4 tb = *(const float4*)(scr1 + ro);
            float  tbw = scr1[ro + 4];
            float ca = 0.f, cb = 0.f;
            #pragma unroll
            for (int u = 0; u < 16; u++) {
                float w = sW011C[(u*9 + t9)*32 + lane];
                ca = fmaf(w, s0_[u], ca);
                cb = fmaf(w, s1_[u], cb);
            }
            A0 = fmaf(ca, ta.x, A0); A1 = fmaf(ca, ta.y, A1);
            A2 = fmaf(ca, ta.z, A2); A3 = fmaf(ca, ta.w, A3);
            A4 = fmaf(ca, taw,  A4);
            B0 = fmaf(cb, tb.x, B0); B1 = fmaf(cb, tb.y, B1);
            B2 = fmaf(cb, tb.z, B2); B3 = fmaf(cb, tb.w, B3);
            B4 = fmaf(cb, tbw,  B4);
        }

        // ---- u1[u][jk] = sum_i t_u[i] C[i*25+jk] (lanes 0..24, both) ----
        if (lane < 25) {
            float c0v = sCt[lane], c1v = sCt[25 + lane], c2v = sCt[50 + lane],
                  c3v = sCt[75 + lane], c4v = sCt[100 + lane];
            #pragma unroll
            for (int u = 0; u < 9; u++) {
                const int ro = ROW8[u];
                float4 ta = *(const float4*)(scr0 + ro);
                float  taw = scr0[ro + 4];
                scr0[U1b + u*25 + lane] = ta.x*c0v + ta.y*c1v + ta.z*c2v + ta.w*c3v + taw*c4v;
                float4 tb = *(const float4*)(scr1 + ro);
                float  tbw = scr1[ro + 4];
                scr1[U1b + u*25 + lane] = tb.x*c0v + tb.y*c1v + tb.z*c2v + tb.w*c3v + tbw*c4v;
            }
        }
        __syncwarp();

        // ---- u2[p][k] = sum_j u1[u][j*5+k] * t_v[j] (both) ----
        #pragma unroll
        for (int r = 0; r < 8; r++) {
            int p = r * 6 + pl;
            if (lane < 30 && p < 45) {
                int t3 = sPairs[p];
                int u25 = t3 & 0xFF, rv = t3 >> 20;
                float ua = 0.f, ub = 0.f;
                #pragma unroll
                for (int j = 0; j < 5; j++) {
                    ua = fmaf(scr0[U1b + u25 + j*5 + kk], scr0[rv + j], ua);
                    ub = fmaf(scr1[U1b + u25 + j*5 + kk], scr1[rv + j], ub);
                }
                scr0[U2b + p*8 + kk] = ua;
                scr1[U2b + p*8 + kk] = ub;
            }
        }
        __syncwarp();

        // ---- h2 term3: sum_p w111S[p][w] * u2[p][k] (both) ----
        #pragma unroll
        for (int p = 0; p < 45; p++) {
            float w = sW111S[p*32 + lane];
            float4 ua = *(const float4*)(scr0 + U2b + p*8);
            float  uaw = scr0[U2b + p*8 + 4];
            A0 = fmaf(w, ua.x, A0); A1 = fmaf(w, ua.y, A1);
            A2 = fmaf(w, ua.z, A2); A3 = fmaf(w, ua.w, A3);
            A4 = fmaf(w, uaw,  A4);
            float4 ub = *(const float4*)(scr1 + U2b + p*8);
            float  ubw = scr1[U2b + p*8 + 4];
            B0 = fmaf(w, ub.x, B0); B1 = fmaf(w, ub.y, B1);
            B2 = fmaf(w, ub.z, B2); B3 = fmaf(w, ub.w, B3);
            B4 = fmaf(w, ubw,  B4);
        }

        // ---- publish h2, h0 (both) ----
        *(float4*)(scr0 + H2b + lane*8) = make_float4(A0, A1, A2, A3);
        scr0[H2b + lane*8 + 4] = A4;
        scr0[H0b + lane] = h0a;
        *(float4*)(scr1 + H2b + lane*8) = make_float4(B0, B1, B2, B3);
        scr1[H2b + lane*8 + 4] = B4;
        scr1[H0b + lane] = h0b;
        __syncwarp();

        // ---- a[w][j] = sum_v v110T[v][w] h2[v][j] (both) ----
        {
            float a0=0.f,a1=0.f,a2=0.f,a3=0.f,a4=0.f;
            float b0=0.f,b1=0.f,b2v=0.f,b3=0.f,b4=0.f;
            #pragma unroll
            for (int v = 0; v < 32; v++) {
                float w = sV110T[v*32 + lane];
                float4 ha = *(const float4*)(scr0 + H2b + v*8);
                float  haw = scr0[H2b + v*8 + 4];
                a0 = fmaf(w, ha.x, a0); a1 = fmaf(w, ha.y, a1);
                a2 = fmaf(w, ha.z, a2); a3 = fmaf(w, ha.w, a3);
                a4 = fmaf(w, haw,  a4);
                float4 hb = *(const float4*)(scr1 + H2b + v*8);
                float  hbw = scr1[H2b + v*8 + 4];
                b0 = fmaf(w, hb.x, b0); b1 = fmaf(w, hb.y, b1);
                b2v = fmaf(w, hb.z, b2v); b3 = fmaf(w, hb.w, b3);
                b4 = fmaf(w, hbw,  b4);
            }
            *(float4*)(scr0 + Ab + lane*8) = make_float4(a0, a1, a2, a3);
            scr0[Ab + lane*8 + 4] = a4;
            *(float4*)(scr1 + Ab + lane*8) = make_float4(b0, b1, b2v, b3);
            scr1[Ab + lane*8 + 4] = b4;
        }

        // ---- r[w] = sum_m VSUM[m][w] * h0[m] (both) ----
        float ra = 0.f, rb = 0.f;
        #pragma unroll
        for (int m = 0; m < 32; m++) {
            float w = sVSUM[m*32 + lane];
            ra = fmaf(w, scr0[H0b + m], ra);
            rb = fmaf(w, scr1[H0b + m], rb);
        }
        __syncwarp();

        // ---- final e0 ----
        {
            float vk0 = ra*A0, vk1 = ra*A1, vk2 = ra*A2, vk3 = ra*A3, vk4 = ra*A4;
            if (lane < 25) {
                float b2 = 0.f;
                #pragma unroll
                for (int u = 0; u < 32; u++)
                    b2 = fmaf(scr0[H2b + u*8 + pl], scr0[Ab + u*8 + kk], b2);
                vk0 = fmaf(b2, sCt[lane*5 + 0], vk0);
                vk1 = fmaf(b2, sCt[lane*5 + 1], vk1);
                vk2 = fmaf(b2, sCt[lane*5 + 2], vk2);
                vk3 = fmaf(b2, sCt[lane*5 + 3], vk3);
                vk4 = fmaf(b2, sCt[lane*5 + 4], vk4);
            }
            #pragma unroll
            for (int off = 16; off > 0; off >>= 1) {
                vk0 += __shfl_xor_sync(0xffffffffu, vk0, off);
                vk1 += __shfl_xor_sync(0xffffffffu, vk1, off);
                vk2 += __shfl_xor_sync(0xffffffffu, vk2, off);
                vk3 += __shfl_xor_sync(0xffffffffu, vk3, off);
                vk4 += __shfl_xor_sync(0xffffffffu, vk4, off);
            }
            if (lane == 0) {
                float* o = outp + (size_t)e0 * 5;
                o[0] = vk0; o[1] = vk1; o[2] = vk2; o[3] = vk3; o[4] = vk4;
            }
        }
        // ---- final e1 ----
        {
            float vk0 = rb*B0, vk1 = rb*B1, vk2 = rb*B2, vk3 = rb*B3, vk4 = rb*B4;
            if (lane < 25) {
                float b2 = 0.f;
                #pragma unroll
                for (int u = 0; u < 32; u++)
                    b2 = fmaf(scr1[H2b + u*8 + pl], scr1[Ab + u*8 + kk], b2);
                vk0 = fmaf(b2, sCt[lane*5 + 0], vk0);
                vk1 = fmaf(b2, sCt[lane*5 + 1], vk1);
                vk2 = fmaf(b2, sCt[lane*5 + 2], vk2);
                vk3 = fmaf(b2, sCt[lane*5 + 3], vk3);
                vk4 = fmaf(b2, sCt[lane*5 + 4], vk4);
            }
            #pragma unroll
            for (int off = 16; off > 0; off >>= 1) {
                vk0 += __shfl_xor_sync(0xffffffffu, vk0, off);
                vk1 += __shfl_xor_sync(0xffffffffu, vk1, off);
                vk2 += __shfl_xor_sync(0xffffffffu, vk2, off);
                vk3 += __shfl_xor_sync(0xffffffffu, vk3, off);
                vk4 += __shfl_xor_sync(0xffffffffu, vk4, off);
            }
            if (lane == 0 && has1) {
                float* o = outp + (size_t)e1 * 5;
                o[0] = vk0; o[1] = vk1; o[2] = vk2; o[3] = vk3; o[4] = vk4;
            }
        }
    }
}

extern "C" void kernel_launch(void* const* d_in, const int* in_sizes, int n_in,
                              void* d_out, int out_size) {
    const float* scalars = (const float*)d_in[0];
    const float* kt      = (const float*)d_in[1];
    const float* w000    = (const float*)d_in[2];
    const float* w110    = (const float*)d_in[3];
    const float* w011    = (const float*)d_in[4];
    const float* w101    = (const float*)d_in[5];
    const float* w111    = (const float*)d_in[6];
    const float* v010    = (const float*)d_in[7];
    const float* v100    = (const float*)d_in[8];
    const float* v110    = (const float*)d_in[9];
    float* out = (float*)d_out;

    int B = in_sizes[0] / 16;
    int NK = (B > 0) ? in_sizes[1] / (B * 5) : 40;

    prep_c_kernel<<<1, 128>>>();
    prep_fold_kernel<<<64, 256>>>(w000, w110, w011, w101, w111, v010, v100, v110);

    cudaFuncSetAttribute(eq_head_kernel, cudaFuncAttributeMaxDynamicSharedMemorySize, SMEM_BYTES);
    eq_head_kernel<<<148, NTHREADS, SMEM_BYTES>>>(scalars, kt, out, B, NK);
}

// round 15
// speedup vs baseline: 1.5459x; 1.1946x over previous
#include <cuda_runtime.h>
#include <math.h>

// C222 sign convention (verified R6): C[2][2][2] > 0.
#define C62_SIGN (+1.0)

// ---- packed weight layout (floats) ----
#define OFF_W000S 0        /* 136*32 */
#define OFF_W110S 4352     /* 45*32  */
#define OFF_W011C 5792     /* 144*32 (w011 + w101^T folded) */
#define OFF_W111S 10400    /* 45*32  */
#define OFF_V110T 11840    /* 32*32  */
#define OFF_VSUM  12864    /* 32*32  */
#define OFF_C     13888    /* 125 pad 128 */
#define WTOT      14016
#define OFF_PAIRS 14016    /* 48 ints */
#define SCRBASE   14064

// ---- per-warp-per-element scratch (floats), liveness-aliased ----
#define ROWb  0            /* 40*8 + 5 sum + pad = 328 */
#define U1b   328          /* 225 pad 228; aliased by Ab later */
#define Gb    556          /* 45 gram; aliased by U2b later */
#define U2b   556          /* 45*8 = 360, ends 916 */
#define Ab    328          /* 32*8 = 256 'a' matrix, written after U2 consumed */
#define H2b   916          /* 32*8 = 256 */
#define H0b   1172         /* 32 */
#define SCR_  1208

#define NWARPS   16
#define NTHREADS 512
#define SMEM_FLOATS (SCRBASE + NWARPS * 2 * SCR_)
#define SMEM_BYTES  (SMEM_FLOATS * 4)

__device__ float gPack[WTOT];

// =======================================================================
// prep_fold: C222 closed-form (block 0) + fold/symmetrize weights (all)
//
// C222 via c[a,b,c] = Tr(S_a S_b S_c) over the symmetric-traceless 3x3
// basis of real Y2 (order m=-2..2: xy, yz, (3z^2-r^2)/sqrt3, xz, x^2-y^2;
// all Tr(S^2)=2). The (2,2,2) invariant subspace is 1-D, so after
// Frobenius-normalization + sign rule (C[2][2][2]>0) this equals the
// reference's SVD-derived tensor exactly (sign convention verified R6/R12).
// =======================================================================
__device__ __forceinline__ void tri_decode(int p, int N, int& u, int& v) {
    int uu = 0, rem = p;
    while (rem >= N - uu) { rem -= N - uu; uu++; }
    u = uu; v = uu + rem;
}

__global__ void prep_fold_kernel(const float* __restrict__ w000, const float* __restrict__ w110,
                                 const float* __restrict__ w011, const float* __restrict__ w101,
                                 const float* __restrict__ w111, const float* __restrict__ v010,
                                 const float* __restrict__ v100, const float* __restrict__ v110)
{
    // ---- block 0: compute C tensor (125 threads) ----
    if (blockIdx.x == 0) {
        __shared__ double sc[125];
        __shared__ double sscale;
        int tid = threadIdx.x;
        if (tid < 125) {
            const double r3 = rsqrt(3.0);
            // S matrices, row-major 3x3, index m+2
            const double S[5][9] = {
                {0,1,0, 1,0,0, 0,0,0},                 // xy
                {0,0,0, 0,0,1, 0,1,0},                 // yz
                {-r3,0,0, 0,-r3,0, 0,0,2.0*r3},        // (3z^2-r^2)/sqrt3
                {0,0,1, 0,0,0, 1,0,0},                 // xz
                {1,0,0, 0,-1,0, 0,0,0}                 // x^2-y^2
            };
            int a = tid / 25, b = (tid / 5) % 5, c = tid % 5;
            // M = S_a * S_b
            double M[9];
            for (int i = 0; i < 3; i++)
                for (int j = 0; j < 3; j++) {
                    double acc = 0.0;
                    for (int k = 0; k < 3; k++) acc += S[a][i*3+k] * S[b][k*3+j];
                    M[i*3+j] = acc;
                }
            // tr(M * S_c)
            double tr = 0.0;
            for (int i = 0; i < 3; i++)
                for (int k = 0; k < 3; k++) tr += M[i*3+k] * S[c][k*3+i];
            sc[tid] = tr;
        }
        __syncthreads();
        if (tid == 0) {
            double n2 = 0.0;
            for (int i = 0; i < 125; i++) n2 += sc[i]*sc[i];
            double sgn = (sc[62] * C62_SIGN > 0.0) ? 1.0 : -1.0;
            sscale = sgn / sqrt(n2);
        }
        __syncthreads();
        if (tid < 125) gPack[OFF_C + tid] = (float)(sc[tid] * sscale);
        if (tid >= 125 && tid < 128) gPack[OFF_C + tid] = 0.f;
    }

    // ---- all blocks: weight folding (grid-stride) ----
    const float c0 = (float)(1.0 / sqrt(337.0));
    const float c2 = (float)sqrt(5.0 / 369.0);
    const float dd = (float)sqrt(5.0 / 3072.0);
    const float i5 = (float)(1.0 / sqrt(5.0));

    int stride = gridDim.x * blockDim.x;
    int t0 = blockIdx.x * blockDim.x + threadIdx.x;

    for (int idx = t0; idx < 136*32; idx += stride) {
        int p = idx >> 5, w = idx & 31, u, v;
        tri_decode(p, 16, u, v);
        float val = (u == v) ? w000[(u*16+u)*32 + w]
                             : (w000[(u*16+v)*32 + w] + w000[(v*16+u)*32 + w]);
        gPack[OFF_W000S + idx] = c0 * val;
    }
    for (int idx = t0; idx < 45*32; idx += stride) {
        int p = idx >> 5, w = idx & 31, u, v;
        tri_decode(p, 9, u, v);
        float v1 = (u == v) ? w110[(u*9+u)*32 + w]
                            : (w110[(u*9+v)*32 + w] + w110[(v*9+u)*32 + w]);
        gPack[OFF_W110S + idx] = (c0 * i5) * v1;
        float v2 = (u == v) ? w111[(u*9+u)*32 + w]
                            : (w111[(u*9+v)*32 + w] + w111[(v*9+u)*32 + w]);
        gPack[OFF_W111S + idx] = c2 * v2;
    }
    for (int idx = t0; idx < 144*32; idx += stride) {
        int r = idx >> 5, w = idx & 31;
        int u = r / 9, t9 = r - u * 9;
        gPack[OFF_W011C + idx] = (c2 * i5) * (w011[idx] + w101[(t9*16 + u)*32 + w]);
    }
    for (int idx = t0; idx < 1024; idx += stride) {
        int u = idx >> 5, v = idx & 31;
        gPack[OFF_V110T + v*32 + u] = dd * v110[idx];
        gPack[OFF_VSUM  + idx]      = (dd * i5) * (v010[idx] + v100[v*32 + u]);
    }
}

// =======================================================================
// main: warp per 2 elements, H=32 -> lanes, weights amortized
// =======================================================================
__global__ void __launch_bounds__(NTHREADS, 1)
eq_head_kernel(const float* __restrict__ scalars, const float* __restrict__ kt,
               float* __restrict__ outp, int NB, int NK)
{
    extern __shared__ float sm[];
    for (int i = threadIdx.x; i < WTOT; i += NTHREADS) sm[i] = gPack[i];
    int* sPairs = (int*)(sm + OFF_PAIRS);
    if (threadIdx.x < 48) {
        int p = threadIdx.x, val = 0;
        if (p < 45) {
            const int RT[9] = {0, 8, 16, 32, 192, 208, 280, 304, 320};
            int u = 0, acc = 0;
            while (acc + (9 - u) <= p) { acc += 9 - u; u++; }
            int v = u + (p - acc);
            val = (u * 25) | (RT[u] << 8) | (RT[v] << 20);
        }
        sPairs[p] = val;
    }
    __syncthreads();

    const float* sW000S = sm + OFF_W000S;
    const float* sW110S = sm + OFF_W110S;
    const float* sW011C = sm + OFF_W011C;
    const float* sW111S = sm + OFF_W111S;
    const float* sV110T = sm + OFF_V110T;
    const float* sVSUM  = sm + OFF_VSUM;
    const float* sCt    = sm + OFF_C;

    const int lane = threadIdx.x & 31;
    const int warp = threadIdx.x >> 5;
    float* scr0 = sm + SCRBASE + warp * (2 * SCR_);
    float* scr1 = scr0 + SCR_;

    const int gw = blockIdx.x * NWARPS + warp;
    const int TW = gridDim.x * NWARPS;
    const int RN = NK * 5;
    const int ROW8[9] = {0, 8, 16, 32, 192, 208, 280, 304, 320};
    const int pl = lane / 5, kk = lane - pl * 5;

    for (int e = gw * 2; e < NB; e += TW * 2) {
        const int e0 = e;
        const int e1 = (e + 1 < NB) ? (e + 1) : e;
        const bool has1 = (e + 1 < NB);

        // ---- load kt rows (R8 layout) for both elements ----
        const float* ke0 = kt + (size_t)e0 * RN;
        const float* ke1 = kt + (size_t)e1 * RN;
        for (int m = lane; m < RN; m += 32) {
            int n = m / 5, i = m - n * 5;
            scr0[n * 8 + i] = __ldg(ke0 + m);
            scr1[n * 8 + i] = __ldg(ke1 + m);
        }
        // ---- scalars to regs ----
        float s0_[16], s1_[16];
        {
            const float4* p0 = (const float4*)(scalars + (size_t)e0 * 16);
            const float4* p1 = (const float4*)(scalars + (size_t)e1 * 16);
            #pragma unroll
            for (int q = 0; q < 4; q++) {
                float4 a = __ldg(p0 + q), b = __ldg(p1 + q);
                s0_[q*4+0]=a.x; s0_[q*4+1]=a.y; s0_[q*4+2]=a.z; s0_[q*4+3]=a.w;
                s1_[q*4+0]=b.x; s1_[q*4+1]=b.y; s1_[q*4+2]=b.z; s1_[q*4+3]=b.w;
            }
        }
        __syncwarp();

        // ---- kernel-sum rows (dual-lane: 0-4 -> e0, 8-12 -> e1) ----
        {
            int li = lane & 7;
            float* sc = (lane < 8) ? scr0 : scr1;
            if (li < 5 && lane < 16) {
                float a = 0.f;
                for (int n = 0; n < NK; n++) a += sc[n * 8 + li];
                sc[320 + li] = a;
            }
        }
        __syncwarp();

        // ---- Gram g[p] for both ----
        #pragma unroll
        for (int r = 0; r < 2; r++) {
            int p = lane + 32 * r;
            if (p < 45) {
                int t3 = sPairs[p];
                int ru = (t3 >> 8) & 0xFFF, rv = t3 >> 20;
                float g0 = 0.f, g1 = 0.f;
                #pragma unroll
                for (int i = 0; i < 5; i++) {
                    g0 = fmaf(scr0[ru + i], scr0[rv + i], g0);
                    g1 = fmaf(scr1[ru + i], scr1[rv + i], g1);
                }
                scr0[Gb + p] = g0;
                scr1[Gb + p] = g1;
            }
        }

        // ---- h0: w000S part (register-only inputs) ----
        float h0a = 0.f, h0b = 0.f;
        {
            int p = 0;
            #pragma unroll
            for (int u = 0; u < 16; u++) {
                #pragma unroll
                for (int v = u; v < 16; v++) {
                    float w = sW000S[p*32 + lane];
                    h0a = fmaf(w, s0_[u]*s0_[v], h0a);
                    h0b = fmaf(w, s1_[u]*s1_[v], h0b);
                    p++;
                }
            }
        }
        __syncwarp();
        #pragma unroll
        for (int p = 0; p < 45; p++) {
            float w = sW110S[p*32 + lane];
            h0a = fmaf(w, scr0[Gb + p], h0a);
            h0b = fmaf(w, scr1[Gb + p], h0b);
        }

        // ---- h2 terms 1+2: folded (w011+w101^T).s times t[k] ----
        float A0=0.f,A1=0.f,A2=0.f,A3=0.f,A4=0.f;
        float B0=0.f,B1=0.f,B2=0.f,B3=0.f,B4=0.f;
        #pragma unroll
        for (int t9 = 0; t9 < 9; t9++) {
            const int ro = ROW8[t9];
            float4 ta = *(const float4*)(scr0 + ro);
            float  taw = scr0[ro + 4];
            float4 tb = *(const float4*)(scr1 + ro);
            float  tbw = scr1[ro + 4];
            float ca = 0.f, cb = 0.f;
            #pragma unroll
            for (int u = 0; u < 16; u++) {
                float w = sW011C[(u*9 + t9)*32 + lane];
                ca = fmaf(w, s0_[u], ca);
                cb = fmaf(w, s1_[u], cb);
            }
            A0 = fmaf(ca, ta.x, A0); A1 = fmaf(ca, ta.y, A1);
            A2 = fmaf(ca, ta.z, A2); A3 = fmaf(ca, ta.w, A3);
            A4 = fmaf(ca, taw,  A4);
            B0 = fmaf(cb, tb.x, B0); B1 = fmaf(cb, tb.y, B1);
            B2 = fmaf(cb, tb.z, B2); B3 = fmaf(cb, tb.w, B3);
            B4 = fmaf(cb, tbw,  B4);
        }

        // ---- u1[u][jk] = sum_i t_u[i] C[i*25+jk] (lanes 0..24, both) ----
        if (lane < 25) {
            float c0v = sCt[lane], c1v = sCt[25 + lane], c2v = sCt[50 + lane],
                  c3v = sCt[75 + lane], c4v = sCt[100 + lane];
            #pragma unroll
            for (int u = 0; u < 9; u++) {
                const int ro = ROW8[u];
                float4 ta = *(const float4*)(scr0 + ro);
                float  taw = scr0[ro + 4];
                scr0[U1b + u*25 + lane] = ta.x*c0v + ta.y*c1v + ta.z*c2v + ta.w*c3v + taw*c4v;
                float4 tb = *(const float4*)(scr1 + ro);
                float  tbw = scr1[ro + 4];
                scr1[U1b + u*25 + lane] = tb.x*c0v + tb.y*c1v + tb.z*c2v + tb.w*c3v + tbw*c4v;
            }
        }
        __syncwarp();

        // ---- u2[p][k] = sum_j u1[u][j*5+k] * t_v[j] (both) ----
        #pragma unroll
        for (int r = 0; r < 8; r++) {
            int p = r * 6 + pl;
            if (lane < 30 && p < 45) {
                int t3 = sPairs[p];
                int u25 = t3 & 0xFF, rv = t3 >> 20;
                float ua = 0.f, ub = 0.f;
                #pragma unroll
                for (int j = 0; j < 5; j++) {
                    ua = fmaf(scr0[U1b + u25 + j*5 + kk], scr0[rv + j], ua);
                    ub = fmaf(scr1[U1b + u25 + j*5 + kk], scr1[rv + j], ub);
                }
                scr0[U2b + p*8 + kk] = ua;
                scr1[U2b + p*8 + kk] = ub;
            }
        }
        __syncwarp();

        // ---- h2 term3: sum_p w111S[p][w] * u2[p][k] (both) ----
        #pragma unroll
        for (int p = 0; p < 45; p++) {
            float w = sW111S[p*32 + lane];
            float4 ua = *(const float4*)(scr0 + U2b + p*8);
            float  uaw = scr0[U2b + p*8 + 4];
            A0 = fmaf(w, ua.x, A0); A1 = fmaf(w, ua.y, A1);
            A2 = fmaf(w, ua.z, A2); A3 = fmaf(w, ua.w, A3);
            A4 = fmaf(w, uaw,  A4);
            float4 ub = *(const float4*)(scr1 + U2b + p*8);
            float  ubw = scr1[U2b + p*8 + 4];
            B0 = fmaf(w, ub.x, B0); B1 = fmaf(w, ub.y, B1);
            B2 = fmaf(w, ub.z, B2); B3 = fmaf(w, ub.w, B3);
            B4 = fmaf(w, ubw,  B4);
        }

        // ---- publish h2, h0 (both) ----
        *(float4*)(scr0 + H2b + lane*8) = make_float4(A0, A1, A2, A3);
        scr0[H2b + lane*8 + 4] = A4;
        scr0[H0b + lane] = h0a;
        *(float4*)(scr1 + H2b + lane*8) = make_float4(B0, B1, B2, B3);
        scr1[H2b + lane*8 + 4] = B4;
        scr1[H0b + lane] = h0b;
        __syncwarp();

        // ---- a[w][j] = sum_v v110T[v][w] h2[v][j] (both) ----
        {
            float a0=0.f,a1=0.f,a2=0.f,a3=0.f,a4=0.f;
            float b0=0.f,b1=0.f,b2v=0.f,b3=0.f,b4=0.f;
            #pragma unroll
            for (int v = 0; v < 32; v++) {
                float w = sV110T[v*32 + lane];
                float4 ha = *(const float4*)(scr0 + H2b + v*8);
                float  haw = scr0[H2b + v*8 + 4];
                a0 = fmaf(w, ha.x, a0); a1 = fmaf(w, ha.y, a1);
                a2 = fmaf(w, ha.z, a2); a3 = fmaf(w, ha.w, a3);
                a4 = fmaf(w, haw,  a4);
                float4 hb = *(const float4*)(scr1 + H2b + v*8);
                float  hbw = scr1[H2b + v*8 + 4];
                b0 = fmaf(w, hb.x, b0); b1 = fmaf(w, hb.y, b1);
                b2v = fmaf(w, hb.z, b2v); b3 = fmaf(w, hb.w, b3);
                b4 = fmaf(w, hbw,  b4);
            }
            *(float4*)(scr0 + Ab + lane*8) = make_float4(a0, a1, a2, a3);
            scr0[Ab + lane*8 + 4] = a4;
            *(float4*)(scr1 + Ab + lane*8) = make_float4(b0, b1, b2v, b3);
            scr1[Ab + lane*8 + 4] = b4;
        }

        // ---- r[w] = sum_m VSUM[m][w] * h0[m] (both) ----
        float ra = 0.f, rb = 0.f;
        #pragma unroll
        for (int m = 0; m < 32; m++) {
            float w = sVSUM[m*32 + lane];
            ra = fmaf(w, scr0[H0b + m], ra);
            rb = fmaf(w, scr1[H0b + m], rb);
        }
        __syncwarp();

        // ---- final e0 ----
        {
            float vk0 = ra*A0, vk1 = ra*A1, vk2 = ra*A2, vk3 = ra*A3, vk4 = ra*A4;
            if (lane < 25) {
                float b2 = 0.f;
                #pragma unroll
                for (int u = 0; u < 32; u++)
                    b2 = fmaf(scr0[H2b + u*8 + pl], scr0[Ab + u*8 + kk], b2);
                vk0 = fmaf(b2, sCt[lane*5 + 0], vk0);
                vk1 = fmaf(b2, sCt[lane*5 + 1], vk1);
                vk2 = fmaf(b2, sCt[lane*5 + 2], vk2);
                vk3 = fmaf(b2, sCt[lane*5 + 3], vk3);
                vk4 = fmaf(b2, sCt[lane*5 + 4], vk4);
            }
            #pragma unroll
            for (int off = 16; off > 0; off >>= 1) {
                vk0 += __shfl_xor_sync(0xffffffffu, vk0, off);
                vk1 += __shfl_xor_sync(0xffffffffu, vk1, off);
                vk2 += __shfl_xor_sync(0xffffffffu, vk2, off);
                vk3 += __shfl_xor_sync(0xffffffffu, vk3, off);
                vk4 += __shfl_xor_sync(0xffffffffu, vk4, off);
            }
            if (lane == 0) {
                float* o = outp + (size_t)e0 * 5;
                o[0] = vk0; o[1] = vk1; o[2] = vk2; o[3] = vk3; o[4] = vk4;
            }
        }
        // ---- final e1 ----
        {
            float vk0 = rb*B0, vk1 = rb*B1, vk2 = rb*B2, vk3 = rb*B3, vk4 = rb*B4;
            if (lane < 25) {
                float b2 = 0.f;
                #pragma unroll
                for (int u = 0; u < 32; u++)
                    b2 = fmaf(scr1[H2b + u*8 + pl], scr1[Ab + u*8 + kk], b2);
                vk0 = fmaf(b2, sCt[lane*5 + 0], vk0);
                vk1 = fmaf(b2, sCt[lane*5 + 1], vk1);
                vk2 = fmaf(b2, sCt[lane*5 + 2], vk2);
                vk3 = fmaf(b2, sCt[lane*5 + 3], vk3);
                vk4 = fmaf(b2, sCt[lane*5 + 4], vk4);
            }
            #pragma unroll
            for (int off = 16; off > 0; off >>= 1) {
                vk0 += __shfl_xor_sync(0xffffffffu, vk0, off);
                vk1 += __shfl_xor_sync(0xffffffffu, vk1, off);
                vk2 += __shfl_xor_sync(0xffffffffu, vk2, off);
                vk3 += __shfl_xor_sync(0xffffffffu, vk3, off);
                vk4 += __shfl_xor_sync(0xffffffffu, vk4, off);
            }
            if (lane == 0 && has1) {
                float* o = outp + (size_t)e1 * 5;
                o[0] = vk0; o[1] = vk1; o[2] = vk2; o[3] = vk3; o[4] = vk4;
            }
        }
    }
}

extern "C" void kernel_launch(void* const* d_in, const int* in_sizes, int n_in,
                              void* d_out, int out_size) {
    const float* scalars = (const float*)d_in[0];
    const float* kt      = (const float*)d_in[1];
    const float* w000    = (const float*)d_in[2];
    const float* w110    = (const float*)d_in[3];
    const float* w011    = (const float*)d_in[4];
    const float* w101    = (const float*)d_in[5];
    const float* w111    = (const float*)d_in[6];
    const float* v010    = (const float*)d_in[7];
    const float* v100    = (const float*)d_in[8];
    const float* v110    = (const float*)d_in[9];
    float* out = (float*)d_out;

    int B = in_sizes[0] / 16;
    int NK = (B > 0) ? in_sizes[1] / (B * 5) : 40;

    prep_fold_kernel<<<64, 256>>>(w000, w110, w011, w101, w111, v010, v100, v110);

    cudaFuncSetAttribute(eq_head_kernel, cudaFuncAttributeMaxDynamicSharedMemorySize, SMEM_BYTES);
    eq_head_kernel<<<148, NTHREADS, SMEM_BYTES>>>(scalars, kt, out, B, NK);
}